// round 13
// baseline (speedup 1.0000x reference)
#include <cuda_runtime.h>
#include <cuda_bf16.h>
#include <cstdint>

#define B_    32
#define C_    256
#define HW    4096
#define NROWS (B_ * C_)
#define NH    5
#define LD    10
#define PROJ  50

// ---------------- scratch (static device memory) --------------------------
__device__ float g_Pq[NROWS * PROJ];
__device__ float g_Pk[NROWS * PROJ];
__device__ float g_Pv[NROWS * PROJ];
__device__ float g_scale[C_];
__device__ float g_shift[C_];
__device__ float g_bnsum[C_];
__device__ float g_bnsum2[C_];
__device__ __nv_bfloat16 g_WT_hi[3][64 * HW];
__device__ __nv_bfloat16 g_WT_lo[3][64 * HW];
__device__ __nv_bfloat16 g_Va2h[NROWS * 64];
__device__ __nv_bfloat16 g_Va2l[NROWS * 64];
__device__ __nv_bfloat16 g_WfcTh[HW * 64];
__device__ __nv_bfloat16 g_WfcTl[HW * 64];

// ---------------- helpers --------------------------------------------------
__device__ __forceinline__ uint32_t smem_u32(const void* p) {
    uint32_t a;
    asm("{ .reg .u64 t; cvta.to.shared.u64 t, %1; cvt.u32.u64 %0, t; }" : "=r"(a) : "l"(p));
    return a;
}
__device__ __forceinline__ void mma16816(float* c, const uint32_t* a, const uint32_t* b) {
    asm volatile("mma.sync.aligned.m16n8k16.row.col.f32.bf16.bf16.f32 "
        "{%0,%1,%2,%3}, {%4,%5,%6,%7}, {%8,%9}, {%0,%1,%2,%3};"
        : "+f"(c[0]), "+f"(c[1]), "+f"(c[2]), "+f"(c[3])
        : "r"(a[0]), "r"(a[1]), "r"(a[2]), "r"(a[3]), "r"(b[0]), "r"(b[1]));
}
__device__ __forceinline__ void ldm_x4(uint32_t* r, uint32_t addr) {
    asm volatile("ldmatrix.sync.aligned.m8n8.x4.shared.b16 {%0,%1,%2,%3}, [%4];"
        : "=r"(r[0]), "=r"(r[1]), "=r"(r[2]), "=r"(r[3]) : "r"(addr));
}
__device__ __forceinline__ void cpasync16(uint32_t dst, const void* src) {
    asm volatile("cp.async.cg.shared.global [%0], [%1], 16;" :: "r"(dst), "l"(src) : "memory");
}
#define CP_COMMIT() asm volatile("cp.async.commit_group;" ::: "memory")
#define CP_WAIT0()  asm volatile("cp.async.wait_group 0;" ::: "memory")

__device__ __forceinline__ void conv_store(float4 x, uint32_t dsth, uint32_t dstl) {
    uint32_t ux = __float_as_uint(x.x), uy = __float_as_uint(x.y);
    uint32_t uz = __float_as_uint(x.z), uw = __float_as_uint(x.w);
    uint32_t hi01 = __byte_perm(ux, uy, 0x7632);
    uint32_t hi23 = __byte_perm(uz, uw, 0x7632);
    float l0 = x.x - __uint_as_float(ux & 0xFFFF0000u);
    float l1 = x.y - __uint_as_float(uy & 0xFFFF0000u);
    float l2 = x.z - __uint_as_float(uz & 0xFFFF0000u);
    float l3 = x.w - __uint_as_float(uw & 0xFFFF0000u);
    __nv_bfloat162 lo01 = __float22bfloat162_rn(make_float2(l0, l1));
    __nv_bfloat162 lo23 = __float22bfloat162_rn(make_float2(l2, l3));
    asm volatile("st.shared.v2.b32 [%0], {%1, %2};"
        :: "r"(dsth), "r"(hi01), "r"(hi23) : "memory");
    asm volatile("st.shared.v2.b32 [%0], {%1, %2};"
        :: "r"(dstl), "r"(*(uint32_t*)&lo01), "r"(*(uint32_t*)&lo23) : "memory");
}

// ================= kernel 0: all weight prep + BN zero ====================
__global__ __launch_bounds__(256) void prep_all_kernel(
    const float* __restrict__ wq, const float* __restrict__ wk,
    const float* __restrict__ wv, const float* __restrict__ wfc)
{
    const int spec = blockIdx.y;
    if (spec < 3) {
        const float* W = (spec == 0) ? wq : (spec == 1) ? wk : wv;
        const int n = blockIdx.x;  // 0..63
        for (int kk = threadIdx.x; kk < HW; kk += 256) {
            float x = (n < PROJ) ? W[(size_t)kk * PROJ + n] : 0.f;
            __nv_bfloat16 h = __float2bfloat16(x);
            float lo = x - __bfloat162float(h);
            g_WT_hi[spec][n * HW + kk] = h;
            g_WT_lo[spec][n * HW + kk] = __float2bfloat16(lo);
        }
    } else {
        if (blockIdx.x == 0) {
            g_bnsum[threadIdx.x] = 0.f;
            g_bnsum2[threadIdx.x] = 0.f;
        }
        const int n0 = blockIdx.x * 64;
#pragma unroll 1
        for (int it = 0; it < 16; it++) {
            int idx = it * 256 + threadIdx.x;
            int kk = idx >> 6;
            int n  = n0 + (idx & 63);
            float x = (kk < PROJ) ? wfc[(size_t)kk * HW + n] : 0.f;
            __nv_bfloat16 h = __float2bfloat16(x);
            float lo = x - __bfloat162float(h);
            g_WfcTh[(size_t)n * 64 + kk] = h;
            g_WfcTl[(size_t)n * 64 + kk] = __float2bfloat16(lo);
        }
    }
}

// ================= kernel 1: proj — PMT=64, 256 thr, warp tile 16x32 ======
// Round-8 schedule/grid (384 CTAs, 73.7KB, 3 CTAs/SM) but 8 warps/CTA
// -> 24 warps/SM for latency hiding.  Warp (wid&3)=m16 tile, (wid>>2)=n32.
#define PMT 64
#define PKC 64
#define PAD 72
#define NCHUNK (HW / PKC)
#define ASZ (64 * PAD)
__global__ __launch_bounds__(256, 3) void proj_mma_kernel(
    const float* __restrict__ q, const float* __restrict__ k,
    const float* __restrict__ v)
{
    extern __shared__ __nv_bfloat16 sm[];
    const int spec = blockIdx.y;
    const float* A = (spec == 0) ? q : (spec == 1) ? k : v;
    const __nv_bfloat16* WTh = g_WT_hi[spec];
    const __nv_bfloat16* WTl = g_WT_lo[spec];
    float* Out = (spec == 0) ? g_Pq : (spec == 1) ? g_Pk : g_Pv;

    const int row0 = blockIdx.x * PMT;
    const int tid  = threadIdx.x;
    const int wid  = tid >> 5, lane = tid & 31;
    const int gr = lane >> 2, tq = lane & 3;

    // smem layout (bytes): Ah0 Ah1 Al0 Al1 Bh0 Bh1 Bl0 Bl1, each ASZ elems
    const uint32_t base = smem_u32(sm);
    const uint32_t sAh0 = base;
    const uint32_t sAl0 = base + 2 * ASZ * 2;
    const uint32_t sBh0 = base + 4 * ASZ * 2;
    const uint32_t sBl0 = base + 6 * ASZ * 2;
    const uint32_t BUFB = ASZ * 2;

    // A conv geometry: 256 thr cover 64x64 fp32: thread rows ar+16j (j=0..3)
    const int ar = tid >> 4, ab = tid & 15;
    const float* Abase = A + (size_t)(row0 + ar) * HW + ab * 4;
    const uint32_t aoff = (uint32_t)(ar * PAD + ab * 4) * 2;

    // B cp.async geometry: rows bn, bn+32
    const int bn = tid >> 3, bk8 = (tid & 7) * 8;
    const uint32_t bd0 = (uint32_t)(bn * PAD + bk8) * 2;
    const uint32_t bd1 = (uint32_t)((bn + 32) * PAD + bk8) * 2;

    // ldmatrix addresses: warp (m,n) = ((wid&3)*16, (wid>>2)*32)
    const int mrow = (wid & 3) * 16;
    const int ncol = (wid >> 2) * 32;
    const int a_row = mrow + (lane & 15);
    const int a_k   = (lane >> 4) << 3;
    const uint32_t lAh = sAh0 + (uint32_t)(a_row * PAD + a_k) * 2;
    const uint32_t lAl = sAl0 + (uint32_t)(a_row * PAD + a_k) * 2;
    const int b_n = ncol + ((lane >> 4) << 3) + (lane & 7);
    const int b_k = ((lane >> 3) & 1) << 3;
    const uint32_t lBh = sBh0 + (uint32_t)(b_n * PAD + b_k) * 2;
    const uint32_t lBl = sBl0 + (uint32_t)(b_n * PAD + b_k) * 2;

    float acc[4][4];
#pragma unroll
    for (int nt = 0; nt < 4; nt++)
#pragma unroll
        for (int i = 0; i < 4; i++) acc[nt][i] = 0.f;

    // ---- prologue: A[0] -> regs, B[0] -> smem buf0 ----
    float4 apref[4];
#pragma unroll
    for (int j = 0; j < 4; j++)
        apref[j] = *(const float4*)(Abase + (size_t)j * 16 * HW);
    cpasync16(sBh0 + bd0, WTh + (size_t)bn * HW + bk8);
    cpasync16(sBh0 + bd1, WTh + (size_t)(bn + 32) * HW + bk8);
    cpasync16(sBl0 + bd0, WTl + (size_t)bn * HW + bk8);
    cpasync16(sBl0 + bd1, WTl + (size_t)(bn + 32) * HW + bk8);
    CP_COMMIT();

    for (int kc = 0; kc < NCHUNK; kc++) {
        const uint32_t bsel = (kc & 1) ? BUFB : 0;
        // ---- convert prefetched A -> smem[buf] ----
#pragma unroll
        for (int j = 0; j < 4; j++) {
            uint32_t d = aoff + j * (16 * PAD * 2);
            conv_store(apref[j], sAh0 + bsel + d, sAl0 + bsel + d);
        }
        // ---- prefetch next A chunk into regs ----
        if (kc + 1 < NCHUNK) {
            const float* An = Abase + (kc + 1) * PKC;
#pragma unroll
            for (int j = 0; j < 4; j++)
                apref[j] = *(const float4*)(An + (size_t)j * 16 * HW);
        }
        CP_WAIT0();
        __syncthreads();
        // ---- issue B[kc+1] into other buffer ----
        if (kc + 1 < NCHUNK) {
            const uint32_t oB = bsel ^ BUFB;
            const int k0n = (kc + 1) * PKC;
            cpasync16(sBh0 + oB + bd0, WTh + (size_t)bn * HW + k0n + bk8);
            cpasync16(sBh0 + oB + bd1, WTh + (size_t)(bn + 32) * HW + k0n + bk8);
            cpasync16(sBl0 + oB + bd0, WTl + (size_t)bn * HW + k0n + bk8);
            cpasync16(sBl0 + oB + bd1, WTl + (size_t)(bn + 32) * HW + k0n + bk8);
            CP_COMMIT();
        }
        // ---- MMA on buf ----
#pragma unroll
        for (int ksi = 0; ksi < 4; ksi++) {
            const uint32_t koff = bsel + ksi * 32;
            uint32_t ah[4], al[4];
            ldm_x4(ah, lAh + koff);
            ldm_x4(al, lAl + koff);
#pragma unroll
            for (int g = 0; g < 2; g++) {
                uint32_t bh4[4], bl4[4];
                const uint32_t boff = g * 16 * (PAD * 2) + koff;
                ldm_x4(bh4, lBh + boff);
                ldm_x4(bl4, lBl + boff);
                mma16816(acc[2 * g],     ah, bh4);
                mma16816(acc[2 * g],     ah, bl4);
                mma16816(acc[2 * g],     al, bh4);
                mma16816(acc[2 * g + 1], ah, bh4 + 2);
                mma16816(acc[2 * g + 1], ah, bl4 + 2);
                mma16816(acc[2 * g + 1], al, bh4 + 2);
            }
        }
    }

    // ---- epilogue ----
    const int r0 = row0 + mrow + gr;
#pragma unroll
    for (int nt = 0; nt < 4; nt++) {
        int col = ncol + nt * 8 + tq * 2;
        if (col < PROJ) {
            Out[(size_t)r0 * PROJ + col]           = acc[nt][0];
            Out[(size_t)r0 * PROJ + col + 1]       = acc[nt][1];
            Out[(size_t)(r0 + 8) * PROJ + col]     = acc[nt][2];
            Out[(size_t)(r0 + 8) * PROJ + col + 1] = acc[nt][3];
        }
    }
}

// ================= kernel 2: 5x5 attention + inner residual ===============
__global__ __launch_bounds__(256) void attn_kernel() {
    const int b = blockIdx.x, tid = threadIdx.x;
    __shared__ float logit_s[NH * NH];
    __shared__ float attn_s[NH * NH];
    if (tid < NH * NH) logit_s[tid] = 0.f;
    __syncthreads();

    const size_t row = (size_t)(b * C_ + tid);
    const size_t rp = row * PROJ;

    float q50[PROJ], k50[PROJ];
#pragma unroll
    for (int t = 0; t < PROJ; t++) { q50[t] = g_Pq[rp + t]; k50[t] = g_Pk[rp + t]; }

#pragma unroll
    for (int i = 0; i < NH; i++)
#pragma unroll
        for (int j = 0; j < NH; j++) {
            float s = 0.f;
#pragma unroll
            for (int l = 0; l < LD; l++) s += q50[i * LD + l] * k50[j * LD + l];
            s += __shfl_xor_sync(~0u, s, 16);
            s += __shfl_xor_sync(~0u, s, 8);
            s += __shfl_xor_sync(~0u, s, 4);
            s += __shfl_xor_sync(~0u, s, 2);
            s += __shfl_xor_sync(~0u, s, 1);
            if ((tid & 31) == 0) atomicAdd(&logit_s[i * NH + j], s);
        }
    __syncthreads();

    if (tid == 0) {
        const float inv = rsqrtf((float)(C_ * LD));
        for (int i = 0; i < NH; i++) {
            float m = -1e30f;
            for (int j = 0; j < NH; j++) m = fmaxf(m, logit_s[i * NH + j] * inv);
            float e[NH], se = 0.f;
            for (int j = 0; j < NH; j++) { e[j] = expf(logit_s[i * NH + j] * inv - m); se += e[j]; }
            float rinv = 1.0f / se;
            for (int j = 0; j < NH; j++) attn_s[i * NH + j] = e[j] * rinv;
        }
    }
    __syncthreads();

    float v50[PROJ];
#pragma unroll
    for (int t = 0; t < PROJ; t++) v50[t] = g_Pv[rp + t];
#pragma unroll
    for (int i = 0; i < NH; i++) {
        float a0 = attn_s[i * NH + 0], a1 = attn_s[i * NH + 1], a2 = attn_s[i * NH + 2],
              a3 = attn_s[i * NH + 3], a4 = attn_s[i * NH + 4];
#pragma unroll
        for (int l = 0; l < LD; l++) {
            float s = v50[i * LD + l]
                + a0 * v50[l] + a1 * v50[LD + l] + a2 * v50[2 * LD + l]
                + a3 * v50[3 * LD + l] + a4 * v50[4 * LD + l];
            __nv_bfloat16 h = __float2bfloat16(s);
            float lo = s - __bfloat162float(h);
            g_Va2h[row * 64 + i * LD + l] = h;
            g_Va2l[row * 64 + i * LD + l] = __float2bfloat16(lo);
        }
    }
}

// ================= kernel 3: fc via mma.sync + residual + BN stats ========
// (round-8 version: direct fragment epilogue — measured 75us)
#define FMT 128
#define FNT 128
__global__ __launch_bounds__(256) void fc_mma_kernel(
    const float* __restrict__ v, float* __restrict__ out)
{
    extern __shared__ char fsm[];
    __nv_bfloat16* Ah = (__nv_bfloat16*)fsm;            // [128][72]
    __nv_bfloat16* Al = Ah + FMT * PAD;
    __nv_bfloat16* Bh = Al + FMT * PAD;
    __nv_bfloat16* Bl = Bh + FNT * PAD;

    const int n0   = blockIdx.x * FNT;
    const int row0 = blockIdx.y * FMT;
    const int tid  = threadIdx.x;
    const int wid  = tid >> 5, lane = tid & 31;
    const int gr = lane >> 2, tq = lane & 3;

#pragma unroll
    for (int j = 0; j < 4; j++) {
        int i = tid + j * 256;
        int r = i >> 3, k8 = (i & 7) * 8;
        *(uint4*)&Ah[r * PAD + k8] = *(const uint4*)&g_Va2h[(size_t)(row0 + r) * 64 + k8];
        *(uint4*)&Al[r * PAD + k8] = *(const uint4*)&g_Va2l[(size_t)(row0 + r) * 64 + k8];
        *(uint4*)&Bh[r * PAD + k8] = *(const uint4*)&g_WfcTh[(size_t)(n0 + r) * 64 + k8];
        *(uint4*)&Bl[r * PAD + k8] = *(const uint4*)&g_WfcTl[(size_t)(n0 + r) * 64 + k8];
    }
    __syncthreads();

    const int a_row = wid * 16 + (lane & 15);
    const int a_k   = (lane >> 4) << 3;
    const uint32_t sAh = smem_u32(&Ah[a_row * PAD + a_k]);
    const uint32_t sAl = smem_u32(&Al[a_row * PAD + a_k]);
    const int b_n = ((lane >> 4) << 3) + (lane & 7);
    const int b_k = ((lane >> 3) & 1) << 3;
    const uint32_t sBh = smem_u32(&Bh[b_n * PAD + b_k]);
    const uint32_t sBl = smem_u32(&Bl[b_n * PAD + b_k]);

    float acc[16][4];
#pragma unroll
    for (int nt = 0; nt < 16; nt++)
#pragma unroll
        for (int i = 0; i < 4; i++) acc[nt][i] = 0.f;

#pragma unroll
    for (int ksi = 0; ksi < 4; ksi++) {
        const uint32_t koff = ksi * 32;
        uint32_t ah[4], al[4];
        ldm_x4(ah, sAh + koff);
        ldm_x4(al, sAl + koff);
#pragma unroll
        for (int g = 0; g < 8; g++) {
            uint32_t bh4[4], bl4[4];
            const uint32_t boff = g * 16 * (PAD * 2) + koff;
            ldm_x4(bh4, sBh + boff);
            ldm_x4(bl4, sBl + boff);
            mma16816(acc[2 * g],     ah, bh4);
            mma16816(acc[2 * g],     ah, bl4);
            mma16816(acc[2 * g],     al, bh4);
            mma16816(acc[2 * g + 1], ah, bh4 + 2);
            mma16816(acc[2 * g + 1], ah, bl4 + 2);
            mma16816(acc[2 * g + 1], al, bh4 + 2);
        }
    }

    const int r0 = row0 + wid * 16 + gr;
    const int r1 = r0 + 8;
    float s0 = 0.f, s20 = 0.f, s1 = 0.f, s21 = 0.f;
#pragma unroll
    for (int nt = 0; nt < 16; nt++) {
        int col = n0 + nt * 8 + tq * 2;
        float2 v0 = *(const float2*)(v + (size_t)r0 * HW + col);
        float2 v1 = *(const float2*)(v + (size_t)r1 * HW + col);
        float o00 = v0.x + acc[nt][0], o01 = v0.y + acc[nt][1];
        float o10 = v1.x + acc[nt][2], o11 = v1.y + acc[nt][3];
        *(float2*)(out + (size_t)r0 * HW + col) = make_float2(o00, o01);
        *(float2*)(out + (size_t)r1 * HW + col) = make_float2(o10, o11);
        s0  += o00 + o01;        s1  += o10 + o11;
        s20 += o00 * o00 + o01 * o01;
        s21 += o10 * o10 + o11 * o11;
    }
    s0  += __shfl_xor_sync(~0u, s0, 1);  s0  += __shfl_xor_sync(~0u, s0, 2);
    s1  += __shfl_xor_sync(~0u, s1, 1);  s1  += __shfl_xor_sync(~0u, s1, 2);
    s20 += __shfl_xor_sync(~0u, s20, 1); s20 += __shfl_xor_sync(~0u, s20, 2);
    s21 += __shfl_xor_sync(~0u, s21, 1); s21 += __shfl_xor_sync(~0u, s21, 2);
    if (tq == 0) {
        atomicAdd(&g_bnsum[r0 & (C_ - 1)], s0);
        atomicAdd(&g_bnsum2[r0 & (C_ - 1)], s20);
        atomicAdd(&g_bnsum[r1 & (C_ - 1)], s1);
        atomicAdd(&g_bnsum2[r1 & (C_ - 1)], s21);
    }
}

// ================= kernel 4: finalize BN scale/shift ======================
__global__ void finalize_kernel(const float* __restrict__ gamma,
                                const float* __restrict__ beta) {
    int ch = threadIdx.x;
    if (ch < C_) {
        const float n = (float)(B_ * HW);
        float mean = g_bnsum[ch] / n;
        float var  = g_bnsum2[ch] / n - mean * mean;
        float sc = gamma[ch] * rsqrtf(var + 1e-5f);
        g_scale[ch] = sc;
        g_shift[ch] = beta[ch] - mean * sc;
    }
}

// ================= kernel 5: apply BN =====================================
__global__ __launch_bounds__(256) void bn_apply_kernel(float* __restrict__ out) {
    size_t idx4 = (size_t)blockIdx.x * 256 + threadIdx.x;
    size_t i = idx4 * 4;
    int ch = (int)((i >> 12) & (C_ - 1));
    float sc = g_scale[ch], sh = g_shift[ch];
    float4 x = *(float4*)(out + i);
    x.x = x.x * sc + sh; x.y = x.y * sc + sh;
    x.z = x.z * sc + sh; x.w = x.w * sc + sh;
    *(float4*)(out + i) = x;
}

extern "C" void kernel_launch(void* const* d_in, const int* in_sizes, int n_in,
                              void* d_out, int out_size) {
    const float* q     = (const float*)d_in[0];
    const float* k     = (const float*)d_in[1];
    const float* v     = (const float*)d_in[2];
    const float* w_q   = (const float*)d_in[3];
    const float* w_k   = (const float*)d_in[4];
    const float* w_v   = (const float*)d_in[5];
    const float* w_fc  = (const float*)d_in[6];
    const float* gamma = (const float*)d_in[7];
    const float* beta  = (const float*)d_in[8];
    float* out = (float*)d_out;

    const int PROJ_SMEM = 8 * ASZ * 2;       // 73728 bytes
    const int FC_SMEM   = 4 * FMT * PAD * 2; // 73728 bytes
    cudaFuncSetAttribute(proj_mma_kernel,
                         cudaFuncAttributeMaxDynamicSharedMemorySize, PROJ_SMEM);
    cudaFuncSetAttribute(fc_mma_kernel,
                         cudaFuncAttributeMaxDynamicSharedMemorySize, FC_SMEM);

    prep_all_kernel<<<dim3(64, 4), 256>>>(w_q, w_k, w_v, w_fc);
    proj_mma_kernel<<<dim3(NROWS / PMT, 3), 256, PROJ_SMEM>>>(q, k, v);
    attn_kernel<<<B_, 256>>>();
    fc_mma_kernel<<<dim3(HW / FNT, NROWS / FMT), 256, FC_SMEM>>>(v, out);
    finalize_kernel<<<1, 256>>>(gamma, beta);
    bn_apply_kernel<<<(NROWS * HW) / (256 * 4), 256>>>(out);
}

// round 14
// speedup vs baseline: 1.5022x; 1.5022x over previous
#include <cuda_runtime.h>
#include <cuda_bf16.h>
#include <cstdint>

#define B_    32
#define C_    256
#define HW    4096
#define NROWS (B_ * C_)
#define NH    5
#define LD    10
#define PROJ  50

// ---------------- scratch (static device memory) --------------------------
__device__ float g_Pq[NROWS * PROJ];
__device__ float g_Pk[NROWS * PROJ];
__device__ float g_Pv[NROWS * PROJ];
__device__ float g_scale[C_];
__device__ float g_shift[C_];
__device__ float g_bnsum[C_];
__device__ float g_bnsum2[C_];
__device__ __nv_bfloat16 g_WT_hi[3][64 * HW];
__device__ __nv_bfloat16 g_WT_lo[3][64 * HW];
__device__ __nv_bfloat16 g_Va2h[NROWS * 64];
__device__ __nv_bfloat16 g_Va2l[NROWS * 64];
__device__ __nv_bfloat16 g_WfcTh[HW * 64];
__device__ __nv_bfloat16 g_WfcTl[HW * 64];

// ---------------- helpers --------------------------------------------------
__device__ __forceinline__ uint32_t smem_u32(const void* p) {
    uint32_t a;
    asm("{ .reg .u64 t; cvta.to.shared.u64 t, %1; cvt.u32.u64 %0, t; }" : "=r"(a) : "l"(p));
    return a;
}
__device__ __forceinline__ void mma16816(float* c, const uint32_t* a, const uint32_t* b) {
    asm volatile("mma.sync.aligned.m16n8k16.row.col.f32.bf16.bf16.f32 "
        "{%0,%1,%2,%3}, {%4,%5,%6,%7}, {%8,%9}, {%0,%1,%2,%3};"
        : "+f"(c[0]), "+f"(c[1]), "+f"(c[2]), "+f"(c[3])
        : "r"(a[0]), "r"(a[1]), "r"(a[2]), "r"(a[3]), "r"(b[0]), "r"(b[1]));
}
__device__ __forceinline__ void ldm_x4(uint32_t* r, uint32_t addr) {
    asm volatile("ldmatrix.sync.aligned.m8n8.x4.shared.b16 {%0,%1,%2,%3}, [%4];"
        : "=r"(r[0]), "=r"(r[1]), "=r"(r[2]), "=r"(r[3]) : "r"(addr));
}
__device__ __forceinline__ void cpasync16(uint32_t dst, const void* src) {
    asm volatile("cp.async.cg.shared.global [%0], [%1], 16;" :: "r"(dst), "l"(src) : "memory");
}
#define CP_COMMIT() asm volatile("cp.async.commit_group;" ::: "memory")
#define CP_WAIT0()  asm volatile("cp.async.wait_group 0;" ::: "memory")

__device__ __forceinline__ void conv_store(float4 x, uint32_t dsth, uint32_t dstl) {
    uint32_t ux = __float_as_uint(x.x), uy = __float_as_uint(x.y);
    uint32_t uz = __float_as_uint(x.z), uw = __float_as_uint(x.w);
    uint32_t hi01 = __byte_perm(ux, uy, 0x7632);
    uint32_t hi23 = __byte_perm(uz, uw, 0x7632);
    float l0 = x.x - __uint_as_float(ux & 0xFFFF0000u);
    float l1 = x.y - __uint_as_float(uy & 0xFFFF0000u);
    float l2 = x.z - __uint_as_float(uz & 0xFFFF0000u);
    float l3 = x.w - __uint_as_float(uw & 0xFFFF0000u);
    __nv_bfloat162 lo01 = __float22bfloat162_rn(make_float2(l0, l1));
    __nv_bfloat162 lo23 = __float22bfloat162_rn(make_float2(l2, l3));
    asm volatile("st.shared.v2.b32 [%0], {%1, %2};"
        :: "r"(dsth), "r"(hi01), "r"(hi23) : "memory");
    asm volatile("st.shared.v2.b32 [%0], {%1, %2};"
        :: "r"(dstl), "r"(*(uint32_t*)&lo01), "r"(*(uint32_t*)&lo23) : "memory");
}

// ================= kernel 0: all weight prep + BN zero ====================
__global__ __launch_bounds__(256) void prep_all_kernel(
    const float* __restrict__ wq, const float* __restrict__ wk,
    const float* __restrict__ wv, const float* __restrict__ wfc)
{
    const int spec = blockIdx.y;
    if (spec < 3) {
        const float* W = (spec == 0) ? wq : (spec == 1) ? wk : wv;
        const int n = blockIdx.x;  // 0..63
        for (int kk = threadIdx.x; kk < HW; kk += 256) {
            float x = (n < PROJ) ? W[(size_t)kk * PROJ + n] : 0.f;
            __nv_bfloat16 h = __float2bfloat16(x);
            float lo = x - __bfloat162float(h);
            g_WT_hi[spec][n * HW + kk] = h;
            g_WT_lo[spec][n * HW + kk] = __float2bfloat16(lo);
        }
    } else {
        if (blockIdx.x == 0) {
            g_bnsum[threadIdx.x] = 0.f;
            g_bnsum2[threadIdx.x] = 0.f;
        }
        const int n0 = blockIdx.x * 64;
#pragma unroll 1
        for (int it = 0; it < 16; it++) {
            int idx = it * 256 + threadIdx.x;
            int kk = idx >> 6;
            int n  = n0 + (idx & 63);
            float x = (kk < PROJ) ? wfc[(size_t)kk * HW + n] : 0.f;
            __nv_bfloat16 h = __float2bfloat16(x);
            float lo = x - __bfloat162float(h);
            g_WfcTh[(size_t)n * 64 + kk] = h;
            g_WfcTl[(size_t)n * 64 + kk] = __float2bfloat16(lo);
        }
    }
}

// ================= kernel 1: proj — warp-specialized producer/consumer ====
// Warps 0-3: round-8 MMA mapping (16 rows x 64 cols each) on buffer cur.
// Warps 4-7: cp.async B[kc+1], convert A[kc+1] into buffer cur^1, prefetch
// A[kc+2].  One __syncthreads per chunk.
#define PMT 64
#define PKC 64
#define PAD 72
#define NCHUNK (HW / PKC)
#define ASZ (64 * PAD)
__global__ __launch_bounds__(256, 3) void proj_mma_kernel(
    const float* __restrict__ q, const float* __restrict__ k,
    const float* __restrict__ v)
{
    extern __shared__ __nv_bfloat16 sm[];
    const int spec = blockIdx.y;
    const float* A = (spec == 0) ? q : (spec == 1) ? k : v;
    const __nv_bfloat16* WTh = g_WT_hi[spec];
    const __nv_bfloat16* WTl = g_WT_lo[spec];
    float* Out = (spec == 0) ? g_Pq : (spec == 1) ? g_Pk : g_Pv;

    const int row0 = blockIdx.x * PMT;
    const int tid  = threadIdx.x;
    const int wid  = tid >> 5, lane = tid & 31;
    const bool consumer = (wid < 4);

    // smem layout (bytes): Ah0 Ah1 Al0 Al1 Bh0 Bh1 Bl0 Bl1, each ASZ elems
    const uint32_t base = smem_u32(sm);
    const uint32_t sAh0 = base;
    const uint32_t sAl0 = base + 2 * ASZ * 2;
    const uint32_t sBh0 = base + 4 * ASZ * 2;
    const uint32_t sBl0 = base + 6 * ASZ * 2;
    const uint32_t BUFB = ASZ * 2;

    if (consumer) {
        // ---------------- consumer warps: MMA ----------------
        const int gr = lane >> 2, tq = lane & 3;
        const int a_row = wid * 16 + (lane & 15);
        const int a_k   = (lane >> 4) << 3;
        const uint32_t lAh = sAh0 + (uint32_t)(a_row * PAD + a_k) * 2;
        const uint32_t lAl = sAl0 + (uint32_t)(a_row * PAD + a_k) * 2;
        const int b_n = ((lane >> 4) << 3) + (lane & 7);
        const int b_k = ((lane >> 3) & 1) << 3;
        const uint32_t lBh = sBh0 + (uint32_t)(b_n * PAD + b_k) * 2;
        const uint32_t lBl = sBl0 + (uint32_t)(b_n * PAD + b_k) * 2;

        float acc[8][4];
#pragma unroll
        for (int nt = 0; nt < 8; nt++)
#pragma unroll
            for (int i = 0; i < 4; i++) acc[nt][i] = 0.f;

        __syncthreads();   // wait for producer prologue (buf0 ready)

        for (int kc = 0; kc < NCHUNK; kc++) {
            const uint32_t bsel = (kc & 1) ? BUFB : 0;
#pragma unroll
            for (int ksi = 0; ksi < 4; ksi++) {
                const uint32_t koff = bsel + ksi * 32;
                uint32_t ah[4], al[4];
                ldm_x4(ah, lAh + koff);
                ldm_x4(al, lAl + koff);
#pragma unroll
                for (int g = 0; g < 4; g++) {
                    uint32_t bh4[4], bl4[4];
                    const uint32_t boff = g * 16 * (PAD * 2) + koff;
                    ldm_x4(bh4, lBh + boff);
                    ldm_x4(bl4, lBl + boff);
                    mma16816(acc[2 * g],     ah, bh4);
                    mma16816(acc[2 * g],     ah, bl4);
                    mma16816(acc[2 * g],     al, bh4);
                    mma16816(acc[2 * g + 1], ah, bh4 + 2);
                    mma16816(acc[2 * g + 1], ah, bl4 + 2);
                    mma16816(acc[2 * g + 1], al, bh4 + 2);
                }
            }
            __syncthreads();
        }

        // ---- epilogue ----
        const int r0 = row0 + wid * 16 + gr;
#pragma unroll
        for (int nt = 0; nt < 8; nt++) {
            int col = nt * 8 + tq * 2;
            if (col < PROJ) {
                Out[(size_t)r0 * PROJ + col]           = acc[nt][0];
                Out[(size_t)r0 * PROJ + col + 1]       = acc[nt][1];
                Out[(size_t)(r0 + 8) * PROJ + col]     = acc[nt][2];
                Out[(size_t)(r0 + 8) * PROJ + col + 1] = acc[nt][3];
            }
        }
    } else {
        // ---------------- producer warps: load + convert ----------------
        const int tid2 = tid - 128;                 // 0..127
        const int ar = tid2 >> 4, ab = tid2 & 15;   // rows ar+8j, cols ab*4
        const float* Abase = A + (size_t)(row0 + ar) * HW + ab * 4;
        const uint32_t aoff = (uint32_t)(ar * PAD + ab * 4) * 2;

        const int bn = tid2 >> 3, bk8 = (tid2 & 7) * 8;

        float4 apref[8];
        // ---- prologue: A[0] -> conv buf0; A[1] -> regs; B[0] -> buf0 ----
#pragma unroll
        for (int j = 0; j < 8; j++)
            apref[j] = *(const float4*)(Abase + (size_t)j * 8 * HW);
#pragma unroll
        for (int j = 0; j < 4; j++) {
            int n = bn + 16 * j;
            uint32_t d = (uint32_t)(n * PAD + bk8) * 2;
            cpasync16(sBh0 + d, WTh + (size_t)n * HW + bk8);
            cpasync16(sBl0 + d, WTl + (size_t)n * HW + bk8);
        }
        CP_COMMIT();
#pragma unroll
        for (int j = 0; j < 8; j++) {
            uint32_t d = aoff + j * (8 * PAD * 2);
            conv_store(apref[j], sAh0 + d, sAl0 + d);
        }
        {
            const float* An = Abase + PKC;
#pragma unroll
            for (int j = 0; j < 8; j++)
                apref[j] = *(const float4*)(An + (size_t)j * 8 * HW);
        }
        CP_WAIT0();
        __syncthreads();   // buf0 published

        for (int kc = 0; kc < NCHUNK; kc++) {
            if (kc + 1 < NCHUNK) {
                const uint32_t oth = ((kc + 1) & 1) ? BUFB : 0;
                const int k0n = (kc + 1) * PKC;
#pragma unroll
                for (int j = 0; j < 4; j++) {
                    int n = bn + 16 * j;
                    uint32_t d = (uint32_t)(n * PAD + bk8) * 2;
                    cpasync16(sBh0 + oth + d, WTh + (size_t)n * HW + k0n + bk8);
                    cpasync16(sBl0 + oth + d, WTl + (size_t)n * HW + k0n + bk8);
                }
                CP_COMMIT();
#pragma unroll
                for (int j = 0; j < 8; j++) {
                    uint32_t d = aoff + j * (8 * PAD * 2);
                    conv_store(apref[j], sAh0 + oth + d, sAl0 + oth + d);
                }
                if (kc + 2 < NCHUNK) {
                    const float* An = Abase + (size_t)(kc + 2) * PKC;
#pragma unroll
                    for (int j = 0; j < 8; j++)
                        apref[j] = *(const float4*)(An + (size_t)j * 8 * HW);
                }
                CP_WAIT0();
            }
            __syncthreads();
        }
    }
}

// ================= kernel 2: 5x5 attention + inner residual ===============
__global__ __launch_bounds__(256) void attn_kernel() {
    const int b = blockIdx.x, tid = threadIdx.x;
    __shared__ float logit_s[NH * NH];
    __shared__ float attn_s[NH * NH];
    if (tid < NH * NH) logit_s[tid] = 0.f;
    __syncthreads();

    const size_t row = (size_t)(b * C_ + tid);
    const size_t rp = row * PROJ;

    float q50[PROJ], k50[PROJ];
#pragma unroll
    for (int t = 0; t < PROJ; t++) { q50[t] = g_Pq[rp + t]; k50[t] = g_Pk[rp + t]; }

#pragma unroll
    for (int i = 0; i < NH; i++)
#pragma unroll
        for (int j = 0; j < NH; j++) {
            float s = 0.f;
#pragma unroll
            for (int l = 0; l < LD; l++) s += q50[i * LD + l] * k50[j * LD + l];
            s += __shfl_xor_sync(~0u, s, 16);
            s += __shfl_xor_sync(~0u, s, 8);
            s += __shfl_xor_sync(~0u, s, 4);
            s += __shfl_xor_sync(~0u, s, 2);
            s += __shfl_xor_sync(~0u, s, 1);
            if ((tid & 31) == 0) atomicAdd(&logit_s[i * NH + j], s);
        }
    __syncthreads();

    if (tid == 0) {
        const float inv = rsqrtf((float)(C_ * LD));
        for (int i = 0; i < NH; i++) {
            float m = -1e30f;
            for (int j = 0; j < NH; j++) m = fmaxf(m, logit_s[i * NH + j] * inv);
            float e[NH], se = 0.f;
            for (int j = 0; j < NH; j++) { e[j] = expf(logit_s[i * NH + j] * inv - m); se += e[j]; }
            float rinv = 1.0f / se;
            for (int j = 0; j < NH; j++) attn_s[i * NH + j] = e[j] * rinv;
        }
    }
    __syncthreads();

    float v50[PROJ];
#pragma unroll
    for (int t = 0; t < PROJ; t++) v50[t] = g_Pv[rp + t];
#pragma unroll
    for (int i = 0; i < NH; i++) {
        float a0 = attn_s[i * NH + 0], a1 = attn_s[i * NH + 1], a2 = attn_s[i * NH + 2],
              a3 = attn_s[i * NH + 3], a4 = attn_s[i * NH + 4];
#pragma unroll
        for (int l = 0; l < LD; l++) {
            float s = v50[i * LD + l]
                + a0 * v50[l] + a1 * v50[LD + l] + a2 * v50[2 * LD + l]
                + a3 * v50[3 * LD + l] + a4 * v50[4 * LD + l];
            __nv_bfloat16 h = __float2bfloat16(s);
            float lo = s - __bfloat162float(h);
            g_Va2h[row * 64 + i * LD + l] = h;
            g_Va2l[row * 64 + i * LD + l] = __float2bfloat16(lo);
        }
    }
}

// ================= kernel 3: fc via mma.sync + residual + BN stats ========
// (round-8 version: direct fragment epilogue — measured 75us)
#define FMT 128
#define FNT 128
__global__ __launch_bounds__(256) void fc_mma_kernel(
    const float* __restrict__ v, float* __restrict__ out)
{
    extern __shared__ char fsm[];
    __nv_bfloat16* Ah = (__nv_bfloat16*)fsm;            // [128][72]
    __nv_bfloat16* Al = Ah + FMT * PAD;
    __nv_bfloat16* Bh = Al + FMT * PAD;
    __nv_bfloat16* Bl = Bh + FNT * PAD;

    const int n0   = blockIdx.x * FNT;
    const int row0 = blockIdx.y * FMT;
    const int tid  = threadIdx.x;
    const int wid  = tid >> 5, lane = tid & 31;
    const int gr = lane >> 2, tq = lane & 3;

#pragma unroll
    for (int j = 0; j < 4; j++) {
        int i = tid + j * 256;
        int r = i >> 3, k8 = (i & 7) * 8;
        *(uint4*)&Ah[r * PAD + k8] = *(const uint4*)&g_Va2h[(size_t)(row0 + r) * 64 + k8];
        *(uint4*)&Al[r * PAD + k8] = *(const uint4*)&g_Va2l[(size_t)(row0 + r) * 64 + k8];
        *(uint4*)&Bh[r * PAD + k8] = *(const uint4*)&g_WfcTh[(size_t)(n0 + r) * 64 + k8];
        *(uint4*)&Bl[r * PAD + k8] = *(const uint4*)&g_WfcTl[(size_t)(n0 + r) * 64 + k8];
    }
    __syncthreads();

    const int a_row = wid * 16 + (lane & 15);
    const int a_k   = (lane >> 4) << 3;
    const uint32_t sAh = smem_u32(&Ah[a_row * PAD + a_k]);
    const uint32_t sAl = smem_u32(&Al[a_row * PAD + a_k]);
    const int b_n = ((lane >> 4) << 3) + (lane & 7);
    const int b_k = ((lane >> 3) & 1) << 3;
    const uint32_t sBh = smem_u32(&Bh[b_n * PAD + b_k]);
    const uint32_t sBl = smem_u32(&Bl[b_n * PAD + b_k]);

    float acc[16][4];
#pragma unroll
    for (int nt = 0; nt < 16; nt++)
#pragma unroll
        for (int i = 0; i < 4; i++) acc[nt][i] = 0.f;

#pragma unroll
    for (int ksi = 0; ksi < 4; ksi++) {
        const uint32_t koff = ksi * 32;
        uint32_t ah[4], al[4];
        ldm_x4(ah, sAh + koff);
        ldm_x4(al, sAl + koff);
#pragma unroll
        for (int g = 0; g < 8; g++) {
            uint32_t bh4[4], bl4[4];
            const uint32_t boff = g * 16 * (PAD * 2) + koff;
            ldm_x4(bh4, sBh + boff);
            ldm_x4(bl4, sBl + boff);
            mma16816(acc[2 * g],     ah, bh4);
            mma16816(acc[2 * g],     ah, bl4);
            mma16816(acc[2 * g],     al, bh4);
            mma16816(acc[2 * g + 1], ah, bh4 + 2);
            mma16816(acc[2 * g + 1], ah, bl4 + 2);
            mma16816(acc[2 * g + 1], al, bh4 + 2);
        }
    }

    const int r0 = row0 + wid * 16 + gr;
    const int r1 = r0 + 8;
    float s0 = 0.f, s20 = 0.f, s1 = 0.f, s21 = 0.f;
#pragma unroll
    for (int nt = 0; nt < 16; nt++) {
        int col = n0 + nt * 8 + tq * 2;
        float2 v0 = *(const float2*)(v + (size_t)r0 * HW + col);
        float2 v1 = *(const float2*)(v + (size_t)r1 * HW + col);
        float o00 = v0.x + acc[nt][0], o01 = v0.y + acc[nt][1];
        float o10 = v1.x + acc[nt][2], o11 = v1.y + acc[nt][3];
        *(float2*)(out + (size_t)r0 * HW + col) = make_float2(o00, o01);
        *(float2*)(out + (size_t)r1 * HW + col) = make_float2(o10, o11);
        s0  += o00 + o01;        s1  += o10 + o11;
        s20 += o00 * o00 + o01 * o01;
        s21 += o10 * o10 + o11 * o11;
    }
    s0  += __shfl_xor_sync(~0u, s0, 1);  s0  += __shfl_xor_sync(~0u, s0, 2);
    s1  += __shfl_xor_sync(~0u, s1, 1);  s1  += __shfl_xor_sync(~0u, s1, 2);
    s20 += __shfl_xor_sync(~0u, s20, 1); s20 += __shfl_xor_sync(~0u, s20, 2);
    s21 += __shfl_xor_sync(~0u, s21, 1); s21 += __shfl_xor_sync(~0u, s21, 2);
    if (tq == 0) {
        atomicAdd(&g_bnsum[r0 & (C_ - 1)], s0);
        atomicAdd(&g_bnsum2[r0 & (C_ - 1)], s20);
        atomicAdd(&g_bnsum[r1 & (C_ - 1)], s1);
        atomicAdd(&g_bnsum2[r1 & (C_ - 1)], s21);
    }
}

// ================= kernel 4: finalize BN scale/shift ======================
__global__ void finalize_kernel(const float* __restrict__ gamma,
                                const float* __restrict__ beta) {
    int ch = threadIdx.x;
    if (ch < C_) {
        const float n = (float)(B_ * HW);
        float mean = g_bnsum[ch] / n;
        float var  = g_bnsum2[ch] / n - mean * mean;
        float sc = gamma[ch] * rsqrtf(var + 1e-5f);
        g_scale[ch] = sc;
        g_shift[ch] = beta[ch] - mean * sc;
    }
}

// ================= kernel 5: apply BN =====================================
__global__ __launch_bounds__(256) void bn_apply_kernel(float* __restrict__ out) {
    size_t idx4 = (size_t)blockIdx.x * 256 + threadIdx.x;
    size_t i = idx4 * 4;
    int ch = (int)((i >> 12) & (C_ - 1));
    float sc = g_scale[ch], sh = g_shift[ch];
    float4 x = *(float4*)(out + i);
    x.x = x.x * sc + sh; x.y = x.y * sc + sh;
    x.z = x.z * sc + sh; x.w = x.w * sc + sh;
    *(float4*)(out + i) = x;
}

extern "C" void kernel_launch(void* const* d_in, const int* in_sizes, int n_in,
                              void* d_out, int out_size) {
    const float* q     = (const float*)d_in[0];
    const float* k     = (const float*)d_in[1];
    const float* v     = (const float*)d_in[2];
    const float* w_q   = (const float*)d_in[3];
    const float* w_k   = (const float*)d_in[4];
    const float* w_v   = (const float*)d_in[5];
    const float* w_fc  = (const float*)d_in[6];
    const float* gamma = (const float*)d_in[7];
    const float* beta  = (const float*)d_in[8];
    float* out = (float*)d_out;

    const int PROJ_SMEM = 8 * ASZ * 2;       // 73728 bytes
    const int FC_SMEM   = 4 * FMT * PAD * 2; // 73728 bytes
    cudaFuncSetAttribute(proj_mma_kernel,
                         cudaFuncAttributeMaxDynamicSharedMemorySize, PROJ_SMEM);
    cudaFuncSetAttribute(fc_mma_kernel,
                         cudaFuncAttributeMaxDynamicSharedMemorySize, FC_SMEM);

    prep_all_kernel<<<dim3(64, 4), 256>>>(w_q, w_k, w_v, w_fc);
    proj_mma_kernel<<<dim3(NROWS / PMT, 3), 256, PROJ_SMEM>>>(q, k, v);
    attn_kernel<<<B_, 256>>>();
    fc_mma_kernel<<<dim3(HW / FNT, NROWS / FMT), 256, FC_SMEM>>>(v, out);
    finalize_kernel<<<1, 256>>>(gamma, beta);
    bn_apply_kernel<<<(NROWS * HW) / (256 * 4), 256>>>(out);
}

// round 16
// speedup vs baseline: 1.5278x; 1.0170x over previous
#include <cuda_runtime.h>
#include <cuda_bf16.h>
#include <cstdint>

#define B_    32
#define C_    256
#define HW    4096
#define NROWS (B_ * C_)
#define NH    5
#define LD    10
#define PROJ  50

// ---------------- scratch (static device memory) --------------------------
__device__ float g_Pq[NROWS * PROJ];
__device__ float g_Pk[NROWS * PROJ];
__device__ float g_Pv[NROWS * PROJ];
__device__ float g_scale[C_];
__device__ float g_shift[C_];
__device__ float g_bnsum[C_];
__device__ float g_bnsum2[C_];
__device__ __nv_bfloat16 g_WT_hi[3][64 * HW];
__device__ __nv_bfloat16 g_WT_lo[3][64 * HW];
__device__ __nv_bfloat16 g_Va2h[NROWS * 64];
__device__ __nv_bfloat16 g_Va2l[NROWS * 64];
__device__ __nv_bfloat16 g_WfcTh[HW * 64];
__device__ __nv_bfloat16 g_WfcTl[HW * 64];

// ---------------- helpers --------------------------------------------------
__device__ __forceinline__ uint32_t smem_u32(const void* p) {
    uint32_t a;
    asm("{ .reg .u64 t; cvta.to.shared.u64 t, %1; cvt.u32.u64 %0, t; }" : "=r"(a) : "l"(p));
    return a;
}
__device__ __forceinline__ void mma16816(float* c, const uint32_t* a, const uint32_t* b) {
    asm volatile("mma.sync.aligned.m16n8k16.row.col.f32.bf16.bf16.f32 "
        "{%0,%1,%2,%3}, {%4,%5,%6,%7}, {%8,%9}, {%0,%1,%2,%3};"
        : "+f"(c[0]), "+f"(c[1]), "+f"(c[2]), "+f"(c[3])
        : "r"(a[0]), "r"(a[1]), "r"(a[2]), "r"(a[3]), "r"(b[0]), "r"(b[1]));
}
__device__ __forceinline__ void ldm_x4(uint32_t* r, uint32_t addr) {
    asm volatile("ldmatrix.sync.aligned.m8n8.x4.shared.b16 {%0,%1,%2,%3}, [%4];"
        : "=r"(r[0]), "=r"(r[1]), "=r"(r[2]), "=r"(r[3]) : "r"(addr));
}
__device__ __forceinline__ void cpasync16(uint32_t dst, const void* src) {
    asm volatile("cp.async.cg.shared.global [%0], [%1], 16;" :: "r"(dst), "l"(src) : "memory");
}
#define CP_COMMIT() asm volatile("cp.async.commit_group;" ::: "memory")
#define CP_WAIT0()  asm volatile("cp.async.wait_group 0;" ::: "memory")

__device__ __forceinline__ void conv_store(float4 x, uint32_t dsth, uint32_t dstl) {
    uint32_t ux = __float_as_uint(x.x), uy = __float_as_uint(x.y);
    uint32_t uz = __float_as_uint(x.z), uw = __float_as_uint(x.w);
    uint32_t hi01 = __byte_perm(ux, uy, 0x7632);
    uint32_t hi23 = __byte_perm(uz, uw, 0x7632);
    float l0 = x.x - __uint_as_float(ux & 0xFFFF0000u);
    float l1 = x.y - __uint_as_float(uy & 0xFFFF0000u);
    float l2 = x.z - __uint_as_float(uz & 0xFFFF0000u);
    float l3 = x.w - __uint_as_float(uw & 0xFFFF0000u);
    __nv_bfloat162 lo01 = __float22bfloat162_rn(make_float2(l0, l1));
    __nv_bfloat162 lo23 = __float22bfloat162_rn(make_float2(l2, l3));
    asm volatile("st.shared.v2.b32 [%0], {%1, %2};"
        :: "r"(dsth), "r"(hi01), "r"(hi23) : "memory");
    asm volatile("st.shared.v2.b32 [%0], {%1, %2};"
        :: "r"(dstl), "r"(*(uint32_t*)&lo01), "r"(*(uint32_t*)&lo23) : "memory");
}

// ================= kernel 0: all weight prep + BN zero ====================
__global__ __launch_bounds__(256) void prep_all_kernel(
    const float* __restrict__ wq, const float* __restrict__ wk,
    const float* __restrict__ wv, const float* __restrict__ wfc)
{
    const int spec = blockIdx.y;
    if (spec < 3) {
        const float* W = (spec == 0) ? wq : (spec == 1) ? wk : wv;
        const int n = blockIdx.x;  // 0..63
        for (int kk = threadIdx.x; kk < HW; kk += 256) {
            float x = (n < PROJ) ? W[(size_t)kk * PROJ + n] : 0.f;
            __nv_bfloat16 h = __float2bfloat16(x);
            float lo = x - __bfloat162float(h);
            g_WT_hi[spec][n * HW + kk] = h;
            g_WT_lo[spec][n * HW + kk] = __float2bfloat16(lo);
        }
    } else {
        if (blockIdx.x == 0) {
            g_bnsum[threadIdx.x] = 0.f;
            g_bnsum2[threadIdx.x] = 0.f;
        }
        const int n0 = blockIdx.x * 64;
#pragma unroll 1
        for (int it = 0; it < 16; it++) {
            int idx = it * 256 + threadIdx.x;
            int kk = idx >> 6;
            int n  = n0 + (idx & 63);
            float x = (kk < PROJ) ? wfc[(size_t)kk * HW + n] : 0.f;
            __nv_bfloat16 h = __float2bfloat16(x);
            float lo = x - __bfloat162float(h);
            g_WfcTh[(size_t)n * 64 + kk] = h;
            g_WfcTl[(size_t)n * 64 + kk] = __float2bfloat16(lo);
        }
    }
}

// ================= kernel 1: proj — warp-specialized, N=56 effective ======
#define PMT 64
#define PKC 64
#define PAD 72
#define NCHUNK (HW / PKC)
#define ASZ (64 * PAD)
__global__ __launch_bounds__(256, 3) void proj_mma_kernel(
    const float* __restrict__ q, const float* __restrict__ k,
    const float* __restrict__ v)
{
    extern __shared__ __nv_bfloat16 sm[];
    const int spec = blockIdx.y;
    const float* A = (spec == 0) ? q : (spec == 1) ? k : v;
    const __nv_bfloat16* WTh = g_WT_hi[spec];
    const __nv_bfloat16* WTl = g_WT_lo[spec];
    float* Out = (spec == 0) ? g_Pq : (spec == 1) ? g_Pk : g_Pv;

    const int row0 = blockIdx.x * PMT;
    const int tid  = threadIdx.x;
    const int wid  = tid >> 5, lane = tid & 31;
    const bool consumer = (wid < 4);

    const uint32_t base = smem_u32(sm);
    const uint32_t sAh0 = base;
    const uint32_t sAl0 = base + 2 * ASZ * 2;
    const uint32_t sBh0 = base + 4 * ASZ * 2;
    const uint32_t sBl0 = base + 6 * ASZ * 2;
    const uint32_t BUFB = ASZ * 2;

    if (consumer) {
        const int gr = lane >> 2, tq = lane & 3;
        const int a_row = wid * 16 + (lane & 15);
        const int a_k   = (lane >> 4) << 3;
        const uint32_t lAh = sAh0 + (uint32_t)(a_row * PAD + a_k) * 2;
        const uint32_t lAl = sAl0 + (uint32_t)(a_row * PAD + a_k) * 2;
        const int b_n = ((lane >> 4) << 3) + (lane & 7);
        const int b_k = ((lane >> 3) & 1) << 3;
        const uint32_t lBh = sBh0 + (uint32_t)(b_n * PAD + b_k) * 2;
        const uint32_t lBl = sBl0 + (uint32_t)(b_n * PAD + b_k) * 2;

        float acc[7][4];
#pragma unroll
        for (int nt = 0; nt < 7; nt++)
#pragma unroll
            for (int i = 0; i < 4; i++) acc[nt][i] = 0.f;

        __syncthreads();   // producer prologue (buf0 ready)

        for (int kc = 0; kc < NCHUNK; kc++) {
            const uint32_t bsel = (kc & 1) ? BUFB : 0;
#pragma unroll
            for (int ksi = 0; ksi < 4; ksi++) {
                const uint32_t koff = bsel + ksi * 32;
                uint32_t ah[4], al[4];
                ldm_x4(ah, lAh + koff);
                ldm_x4(al, lAl + koff);
#pragma unroll
                for (int g = 0; g < 4; g++) {
                    uint32_t bh4[4], bl4[4];
                    const uint32_t boff = g * 16 * (PAD * 2) + koff;
                    ldm_x4(bh4, lBh + boff);
                    ldm_x4(bl4, lBl + boff);
                    mma16816(acc[2 * g],     ah, bh4);
                    mma16816(acc[2 * g],     ah, bl4);
                    mma16816(acc[2 * g],     al, bh4);
                    if (g < 3) {   // tile 7 (cols 56-63) is pure padding
                        mma16816(acc[2 * g + 1], ah, bh4 + 2);
                        mma16816(acc[2 * g + 1], ah, bl4 + 2);
                        mma16816(acc[2 * g + 1], al, bh4 + 2);
                    }
                }
            }
            __syncthreads();
        }

        const int r0 = row0 + wid * 16 + gr;
#pragma unroll
        for (int nt = 0; nt < 7; nt++) {
            int col = nt * 8 + tq * 2;
            if (col < PROJ) {
                Out[(size_t)r0 * PROJ + col]           = acc[nt][0];
                Out[(size_t)r0 * PROJ + col + 1]       = acc[nt][1];
                Out[(size_t)(r0 + 8) * PROJ + col]     = acc[nt][2];
                Out[(size_t)(r0 + 8) * PROJ + col + 1] = acc[nt][3];
            }
        }
    } else {
        const int tid2 = tid - 128;
        const int ar = tid2 >> 4, ab = tid2 & 15;
        const float* Abase = A + (size_t)(row0 + ar) * HW + ab * 4;
        const uint32_t aoff = (uint32_t)(ar * PAD + ab * 4) * 2;

        const int bn = tid2 >> 3, bk8 = (tid2 & 7) * 8;

        float4 apref[8];
#pragma unroll
        for (int j = 0; j < 8; j++)
            apref[j] = *(const float4*)(Abase + (size_t)j * 8 * HW);
#pragma unroll
        for (int j = 0; j < 4; j++) {
            int n = bn + 16 * j;
            if (n < 56) {
                uint32_t d = (uint32_t)(n * PAD + bk8) * 2;
                cpasync16(sBh0 + d, WTh + (size_t)n * HW + bk8);
                cpasync16(sBl0 + d, WTl + (size_t)n * HW + bk8);
            }
        }
        CP_COMMIT();
#pragma unroll
        for (int j = 0; j < 8; j++) {
            uint32_t d = aoff + j * (8 * PAD * 2);
            conv_store(apref[j], sAh0 + d, sAl0 + d);
        }
        {
            const float* An = Abase + PKC;
#pragma unroll
            for (int j = 0; j < 8; j++)
                apref[j] = *(const float4*)(An + (size_t)j * 8 * HW);
        }
        CP_WAIT0();
        __syncthreads();

        for (int kc = 0; kc < NCHUNK; kc++) {
            if (kc + 1 < NCHUNK) {
                const uint32_t oth = ((kc + 1) & 1) ? BUFB : 0;
                const int k0n = (kc + 1) * PKC;
#pragma unroll
                for (int j = 0; j < 4; j++) {
                    int n = bn + 16 * j;
                    if (n < 56) {
                        uint32_t d = (uint32_t)(n * PAD + bk8) * 2;
                        cpasync16(sBh0 + oth + d, WTh + (size_t)n * HW + k0n + bk8);
                        cpasync16(sBl0 + oth + d, WTl + (size_t)n * HW + k0n + bk8);
                    }
                }
                CP_COMMIT();
#pragma unroll
                for (int j = 0; j < 8; j++) {
                    uint32_t d = aoff + j * (8 * PAD * 2);
                    conv_store(apref[j], sAh0 + oth + d, sAl0 + oth + d);
                }
                if (kc + 2 < NCHUNK) {
                    const float* An = Abase + (size_t)(kc + 2) * PKC;
#pragma unroll
                    for (int j = 0; j < 8; j++)
                        apref[j] = *(const float4*)(An + (size_t)j * 8 * HW);
                }
                CP_WAIT0();
            }
            __syncthreads();
        }
    }
}

// ================= kernel 2: 5x5 attention + inner residual ===============
__global__ __launch_bounds__(256) void attn_kernel() {
    const int b = blockIdx.x, tid = threadIdx.x;
    __shared__ float logit_s[NH * NH];
    __shared__ float attn_s[NH * NH];
    if (tid < NH * NH) logit_s[tid] = 0.f;
    __syncthreads();

    const size_t row = (size_t)(b * C_ + tid);
    const size_t rp = row * PROJ;

    float q50[PROJ], k50[PROJ];
#pragma unroll
    for (int t = 0; t < PROJ; t++) { q50[t] = g_Pq[rp + t]; k50[t] = g_Pk[rp + t]; }

#pragma unroll
    for (int i = 0; i < NH; i++)
#pragma unroll
        for (int j = 0; j < NH; j++) {
            float s = 0.f;
#pragma unroll
            for (int l = 0; l < LD; l++) s += q50[i * LD + l] * k50[j * LD + l];
            s += __shfl_xor_sync(~0u, s, 16);
            s += __shfl_xor_sync(~0u, s, 8);
            s += __shfl_xor_sync(~0u, s, 4);
            s += __shfl_xor_sync(~0u, s, 2);
            s += __shfl_xor_sync(~0u, s, 1);
            if ((tid & 31) == 0) atomicAdd(&logit_s[i * NH + j], s);
        }
    __syncthreads();

    if (tid == 0) {
        const float inv = rsqrtf((float)(C_ * LD));
        for (int i = 0; i < NH; i++) {
            float m = -1e30f;
            for (int j = 0; j < NH; j++) m = fmaxf(m, logit_s[i * NH + j] * inv);
            float e[NH], se = 0.f;
            for (int j = 0; j < NH; j++) { e[j] = expf(logit_s[i * NH + j] * inv - m); se += e[j]; }
            float rinv = 1.0f / se;
            for (int j = 0; j < NH; j++) attn_s[i * NH + j] = e[j] * rinv;
        }
    }
    __syncthreads();

    float v50[PROJ];
#pragma unroll
    for (int t = 0; t < PROJ; t++) v50[t] = g_Pv[rp + t];
#pragma unroll
    for (int i = 0; i < NH; i++) {
        float a0 = attn_s[i * NH + 0], a1 = attn_s[i * NH + 1], a2 = attn_s[i * NH + 2],
              a3 = attn_s[i * NH + 3], a4 = attn_s[i * NH + 4];
#pragma unroll
        for (int l = 0; l < LD; l++) {
            float s = v50[i * LD + l]
                + a0 * v50[l] + a1 * v50[LD + l] + a2 * v50[2 * LD + l]
                + a3 * v50[3 * LD + l] + a4 * v50[4 * LD + l];
            __nv_bfloat16 h = __float2bfloat16(s);
            float lo = s - __bfloat162float(h);
            g_Va2h[row * 64 + i * LD + l] = h;
            g_Va2l[row * 64 + i * LD + l] = __float2bfloat16(lo);
        }
    }
}

// ================= kernel 3: fc — permuted-B float4 epilogue ==============
// B smem row r = tile*8 + f feeds global col G(r):
//   j = r>>4 (tile pair), p = (r>>3)&1, tq = (r&7)>>1, e = r&1
//   G(r) = j*16 + tq*4 + p*2 + e   (bijection on 0..127)
// Thread (gr,tq) then owns float4 at col n0 + j*16 + tq*4 for rows r0, r1.
#define FMT 128
#define FNT 128
__device__ __forceinline__ int fc_perm(int r) {
    return ((r >> 4) << 4) + (((r & 7) >> 1) << 2) + (((r >> 3) & 1) << 1) + (r & 1);
}
__global__ __launch_bounds__(256) void fc_mma_kernel(
    const float* __restrict__ v, float* __restrict__ out)
{
    extern __shared__ char fsm[];
    __nv_bfloat16* Ah = (__nv_bfloat16*)fsm;            // [128][72]
    __nv_bfloat16* Al = Ah + FMT * PAD;
    __nv_bfloat16* Bh = Al + FMT * PAD;
    __nv_bfloat16* Bl = Bh + FNT * PAD;

    const int n0   = blockIdx.x * FNT;
    const int row0 = blockIdx.y * FMT;
    const int tid  = threadIdx.x;
    const int wid  = tid >> 5, lane = tid & 31;
    const int gr = lane >> 2, tq = lane & 3;

#pragma unroll
    for (int j = 0; j < 4; j++) {
        int i = tid + j * 256;
        int r = i >> 3, k8 = (i & 7) * 8;
        int gcol = n0 + fc_perm(r);
        *(uint4*)&Ah[r * PAD + k8] = *(const uint4*)&g_Va2h[(size_t)(row0 + r) * 64 + k8];
        *(uint4*)&Al[r * PAD + k8] = *(const uint4*)&g_Va2l[(size_t)(row0 + r) * 64 + k8];
        *(uint4*)&Bh[r * PAD + k8] = *(const uint4*)&g_WfcTh[(size_t)gcol * 64 + k8];
        *(uint4*)&Bl[r * PAD + k8] = *(const uint4*)&g_WfcTl[(size_t)gcol * 64 + k8];
    }
    __syncthreads();

    const int a_row = wid * 16 + (lane & 15);
    const int a_k   = (lane >> 4) << 3;
    const uint32_t sAh = smem_u32(&Ah[a_row * PAD + a_k]);
    const uint32_t sAl = smem_u32(&Al[a_row * PAD + a_k]);
    const int b_n = ((lane >> 4) << 3) + (lane & 7);
    const int b_k = ((lane >> 3) & 1) << 3;
    const uint32_t sBh = smem_u32(&Bh[b_n * PAD + b_k]);
    const uint32_t sBl = smem_u32(&Bl[b_n * PAD + b_k]);

    float acc[16][4];
#pragma unroll
    for (int nt = 0; nt < 16; nt++)
#pragma unroll
        for (int i = 0; i < 4; i++) acc[nt][i] = 0.f;

#pragma unroll
    for (int ksi = 0; ksi < 4; ksi++) {
        const uint32_t koff = ksi * 32;
        uint32_t ah[4], al[4];
        ldm_x4(ah, sAh + koff);
        ldm_x4(al, sAl + koff);
#pragma unroll
        for (int g = 0; g < 8; g++) {
            uint32_t bh4[4], bl4[4];
            const uint32_t boff = g * 16 * (PAD * 2) + koff;
            ldm_x4(bh4, sBh + boff);
            ldm_x4(bl4, sBl + boff);
            mma16816(acc[2 * g],     ah, bh4);
            mma16816(acc[2 * g],     ah, bl4);
            mma16816(acc[2 * g],     al, bh4);
            mma16816(acc[2 * g + 1], ah, bh4 + 2);
            mma16816(acc[2 * g + 1], ah, bl4 + 2);
            mma16816(acc[2 * g + 1], al, bh4 + 2);
        }
    }

    // ---- epilogue: thread owns float4 at col n0 + j*16 + tq*4, rows r0/r1 ----
    const int r0 = row0 + wid * 16 + gr;
    const int r1 = r0 + 8;
    float s0 = 0.f, s20 = 0.f, s1 = 0.f, s21 = 0.f;
#pragma unroll
    for (int j = 0; j < 8; j++) {
        const int col = n0 + j * 16 + tq * 4;
        float4 v0 = *(const float4*)(v + (size_t)r0 * HW + col);
        float4 v1 = *(const float4*)(v + (size_t)r1 * HW + col);
        float4 o0, o1;
        o0.x = v0.x + acc[2 * j][0];     o0.y = v0.y + acc[2 * j][1];
        o0.z = v0.z + acc[2 * j + 1][0]; o0.w = v0.w + acc[2 * j + 1][1];
        o1.x = v1.x + acc[2 * j][2];     o1.y = v1.y + acc[2 * j][3];
        o1.z = v1.z + acc[2 * j + 1][2]; o1.w = v1.w + acc[2 * j + 1][3];
        *(float4*)(out + (size_t)r0 * HW + col) = o0;
        *(float4*)(out + (size_t)r1 * HW + col) = o1;
        s0  += o0.x + o0.y + o0.z + o0.w;
        s1  += o1.x + o1.y + o1.z + o1.w;
        s20 += o0.x * o0.x + o0.y * o0.y + o0.z * o0.z + o0.w * o0.w;
        s21 += o1.x * o1.x + o1.y * o1.y + o1.z * o1.z + o1.w * o1.w;
    }
    s0  += __shfl_xor_sync(~0u, s0, 1);  s0  += __shfl_xor_sync(~0u, s0, 2);
    s1  += __shfl_xor_sync(~0u, s1, 1);  s1  += __shfl_xor_sync(~0u, s1, 2);
    s20 += __shfl_xor_sync(~0u, s20, 1); s20 += __shfl_xor_sync(~0u, s20, 2);
    s21 += __shfl_xor_sync(~0u, s21, 1); s21 += __shfl_xor_sync(~0u, s21, 2);
    if (tq == 0) {
        atomicAdd(&g_bnsum[r0 & (C_ - 1)], s0);
        atomicAdd(&g_bnsum2[r0 & (C_ - 1)], s20);
        atomicAdd(&g_bnsum[r1 & (C_ - 1)], s1);
        atomicAdd(&g_bnsum2[r1 & (C_ - 1)], s21);
    }
}

// ================= kernel 4: finalize BN scale/shift ======================
__global__ void finalize_kernel(const float* __restrict__ gamma,
                                const float* __restrict__ beta) {
    int ch = threadIdx.x;
    if (ch < C_) {
        const float n = (float)(B_ * HW);
        float mean = g_bnsum[ch] / n;
        float var  = g_bnsum2[ch] / n - mean * mean;
        float sc = gamma[ch] * rsqrtf(var + 1e-5f);
        g_scale[ch] = sc;
        g_shift[ch] = beta[ch] - mean * sc;
    }
}

// ================= kernel 5: apply BN =====================================
__global__ __launch_bounds__(256) void bn_apply_kernel(float* __restrict__ out) {
    size_t idx4 = (size_t)blockIdx.x * 256 + threadIdx.x;
    size_t i = idx4 * 4;
    int ch = (int)((i >> 12) & (C_ - 1));
    float sc = g_scale[ch], sh = g_shift[ch];
    float4 x = *(float4*)(out + i);
    x.x = x.x * sc + sh; x.y = x.y * sc + sh;
    x.z = x.z * sc + sh; x.w = x.w * sc + sh;
    *(float4*)(out + i) = x;
}

extern "C" void kernel_launch(void* const* d_in, const int* in_sizes, int n_in,
                              void* d_out, int out_size) {
    const float* q     = (const float*)d_in[0];
    const float* k     = (const float*)d_in[1];
    const float* v     = (const float*)d_in[2];
    const float* w_q   = (const float*)d_in[3];
    const float* w_k   = (const float*)d_in[4];
    const float* w_v   = (const float*)d_in[5];
    const float* w_fc  = (const float*)d_in[6];
    const float* gamma = (const float*)d_in[7];
    const float* beta  = (const float*)d_in[8];
    float* out = (float*)d_out;

    const int PROJ_SMEM = 8 * ASZ * 2;       // 73728 bytes
    const int FC_SMEM   = 4 * FMT * PAD * 2; // 73728 bytes
    cudaFuncSetAttribute(proj_mma_kernel,
                         cudaFuncAttributeMaxDynamicSharedMemorySize, PROJ_SMEM);
    cudaFuncSetAttribute(fc_mma_kernel,
                         cudaFuncAttributeMaxDynamicSharedMemorySize, FC_SMEM);

    prep_all_kernel<<<dim3(64, 4), 256>>>(w_q, w_k, w_v, w_fc);
    proj_mma_kernel<<<dim3(NROWS / PMT, 3), 256, PROJ_SMEM>>>(q, k, v);
    attn_kernel<<<B_, 256>>>();
    fc_mma_kernel<<<dim3(HW / FNT, NROWS / FMT), 256, FC_SMEM>>>(v, out);
    finalize_kernel<<<1, 256>>>(gamma, beta);
    bn_apply_kernel<<<(NROWS * HW) / (256 * 4), 256>>>(out);
}